// round 10
// baseline (speedup 1.0000x reference)
#include <cuda_runtime.h>

#define NB_DIMS 128
#define BATCH   16384

// One warp per sample (empirically best: max warp-level parallelism).
// u32 byte-offset addressing (512MB table fits u32): idx->address is one
// IMAD, shortening the serial prologue. Default __ldg caching preserves
// cross-replay L2 reuse (R6 lesson: __ldcs broke it).
__global__ void __launch_bounds__(256) sgns_dot_kernel(
    const int*   __restrict__ vii,   // [BATCH, 2] int32
    const float* __restrict__ W,     // [NB_VECS, 128] f32
    float*       __restrict__ out)   // [BATCH] f32
{
    int gtid = blockIdx.x * blockDim.x + threadIdx.x;
    int warp = gtid >> 5;
    int lane = gtid & 31;
    if (warp >= BATCH) return;

    // Both indices in one broadcast 8B load.
    int2 idx = __ldg(reinterpret_cast<const int2*>(vii) + warp);

    const char* Wb = reinterpret_cast<const char*>(W);
    unsigned lb   = (unsigned)(lane * 16);
    unsigned off0 = (unsigned)idx.x * 512u + lb;   // 512 B per row
    unsigned off1 = (unsigned)idx.y * 512u + lb;

    // Two independent 16B gathers, default caching.
    float4 a = __ldg(reinterpret_cast<const float4*>(Wb + off0));
    float4 b = __ldg(reinterpret_cast<const float4*>(Wb + off1));

    float s = a.x * b.x + a.y * b.y + a.z * b.z + a.w * b.w;

    #pragma unroll
    for (int o = 16; o > 0; o >>= 1)
        s += __shfl_xor_sync(0xffffffffu, s, o);

    if (lane == 0) out[warp] = s;
}

extern "C" void kernel_launch(void* const* d_in, const int* in_sizes, int n_in,
                              void* d_out, int out_size)
{
    const void* p0 = d_in[0];
    const void* p1 = d_in[1];
    const int*   vii;
    const float* W;
    if (in_sizes[0] < in_sizes[1]) {
        vii = (const int*)p0;  W = (const float*)p1;
    } else {
        vii = (const int*)p1;  W = (const float*)p0;
    }
    float* out = (float*)d_out;

    const int threads = 256;                       // 8 warps/block
    const int blocks  = (BATCH * 32) / threads;    // 2048 blocks
    sgns_dot_kernel<<<blocks, threads>>>(vii, W, out);
}

// round 12
// speedup vs baseline: 1.0435x; 1.0435x over previous
#include <cuda_runtime.h>

#define NB_DIMS 128
#define BATCH   16384

// Converged config: one warp per sample (max warp-level parallelism — beat
// every multi-sample-per-warp variant), 256-thread blocks, default __ldg
// caching (preserves cross-replay L2 reuse; __ldcs regressed it). Grid
// exactly covers BATCH warps, so no bounds guard: shortest possible
// prologue (idx broadcast -> 2 independent LDG.128 -> dot -> 5 shfl).
__global__ void __launch_bounds__(256) sgns_dot_kernel(
    const int*   __restrict__ vii,   // [BATCH, 2] int32
    const float* __restrict__ W,     // [NB_VECS, 128] f32
    float*       __restrict__ out)   // [BATCH] f32
{
    int gtid = blockIdx.x * blockDim.x + threadIdx.x;
    int warp = gtid >> 5;            // in [0, BATCH) by construction
    int lane = gtid & 31;

    // Both indices in one broadcast 8B load.
    int2 idx = __ldg(reinterpret_cast<const int2*>(vii) + warp);

    const float4* __restrict__ r0 =
        reinterpret_cast<const float4*>(W + (long long)idx.x * NB_DIMS);
    const float4* __restrict__ r1 =
        reinterpret_cast<const float4*>(W + (long long)idx.y * NB_DIMS);

    // Two independent 16B gathers (fully coalesced: warp covers the 512B row).
    float4 a = __ldg(r0 + lane);
    float4 b = __ldg(r1 + lane);

    float s = a.x * b.x + a.y * b.y + a.z * b.z + a.w * b.w;

    #pragma unroll
    for (int o = 16; o > 0; o >>= 1)
        s += __shfl_down_sync(0xffffffffu, s, o);

    if (lane == 0) out[warp] = s;
}

extern "C" void kernel_launch(void* const* d_in, const int* in_sizes, int n_in,
                              void* d_out, int out_size)
{
    const void* p0 = d_in[0];
    const void* p1 = d_in[1];
    const int*   vii;
    const float* W;
    if (in_sizes[0] < in_sizes[1]) {
        vii = (const int*)p0;  W = (const float*)p1;
    } else {
        vii = (const int*)p1;  W = (const float*)p0;
    }
    float* out = (float*)d_out;

    const int threads = 256;                       // 8 warps/block
    const int blocks  = (BATCH * 32) / threads;    // 2048 blocks, exact cover
    sgns_dot_kernel<<<blocks, threads>>>(vii, W, out);
}